// round 14
// baseline (speedup 1.0000x reference)
#include <cuda_runtime.h>
#include <cuda_bf16.h>
#include <cuda_fp16.h>
#include <cstdint>

// Problem constants (fixed by the dataset)
#define NMAX 50000
#define CIN  128
#define C2   256
#define COUT 128
#define KNB  16

// Scratch (static device arrays; no allocation):
__device__ __half g_eq[(size_t)NMAX * 512];       // [node]: 256 e | 256 q (fp16)
__device__ __nv_bfloat16 g_fh[(size_t)NMAX * 256]; // feat hi (bf16)
__device__ __nv_bfloat16 g_fl[(size_t)NMAX * 256]; // feat lo
__device__ __nv_bfloat16 g_W1h[256 * 128];        // W1^T hi  [n][k]
__device__ __nv_bfloat16 g_W1l[256 * 128];
__device__ __nv_bfloat16 g_Wsh[256 * 256];        // Ws^T hi  [n][k]
__device__ __nv_bfloat16 g_Wsl[256 * 256];
__device__ __nv_bfloat16 g_Wmh[128 * 256];        // Wm^T hi  [n][k]
__device__ __nv_bfloat16 g_Wml[128 * 256];
__device__ int g_idx64;

// ---------------------------------------------------------------------------
// mma.sync m16n8k16 bf16 (baseline PTX, valid on compute_103 virtual arch)
// ---------------------------------------------------------------------------
__device__ __forceinline__ void mma16816(float* d,
    uint32_t a0, uint32_t a1, uint32_t a2, uint32_t a3,
    uint32_t b0, uint32_t b1)
{
    asm volatile(
        "mma.sync.aligned.m16n8k16.row.col.f32.bf16.bf16.f32 "
        "{%0,%1,%2,%3}, {%4,%5,%6,%7}, {%8,%9}, {%0,%1,%2,%3};"
        : "+f"(d[0]), "+f"(d[1]), "+f"(d[2]), "+f"(d[3])
        : "r"(a0), "r"(a1), "r"(a2), "r"(a3), "r"(b0), "r"(b1));
}

// SMEM layout for kernelA (bytes). Strides 272/528 ≡ 4 mod 32 words.
#define XS   272
#define XH_OFF 0
#define XL_OFF 17408              // 64*272
#define YS   528
#define YSH_OFF 0
#define YSL_OFF 33792             // 64*528
#define WS   272
#define W_OFF 69632
#define WHL  69632                // 256*272
#define PAR_OFF 208896
#define SMEM_TOTAL 212992

// SMEM layout for kernelC v2 (feat only)
#define C_FH  0                   // feat hi: 64*528 = 33792
#define C_FL  33792               // feat lo
#define C_SMEM 67584

// ---------------------------------------------------------------------------
// Prep: pack W1^T, Ws^T, Wm^T bf16 hi/lo, [n][k]; idx dtype detect. 128 blks.
// ---------------------------------------------------------------------------
__global__ __launch_bounds__(256) void prep_kernel(
    const float* __restrict__ W1,
    const float* __restrict__ Ws,
    const float* __restrict__ Wm,
    const unsigned int* __restrict__ idxraw)
{
    const int b = blockIdx.x, tid = threadIdx.x;
    if (b == 0 && tid == 0) {   // int64 -> every odd 32-bit word zero
        int is64 = 1;
        #pragma unroll 1
        for (int t = 1; t < 256; t += 2)
            if (idxraw[t] != 0u) { is64 = 0; break; }
        g_idx64 = is64;
    }
    if (b < 32) {                // W1: 32768 elems, 1024 per block
        #pragma unroll
        for (int i = 0; i < 4; i++) {
            int idx = b * 1024 + tid + i * 256;
            int k = idx >> 8, n = idx & 255;
            float v = W1[(size_t)k * 256 + n];
            __nv_bfloat16 hi = __float2bfloat16(v);
            g_W1h[n * 128 + k] = hi;
            g_W1l[n * 128 + k] = __float2bfloat16(v - __bfloat162float(hi));
        }
    } else if (b < 96) {         // Ws: 65536 elems, blocks 32..95
        #pragma unroll
        for (int i = 0; i < 4; i++) {
            int idx = (b - 32) * 1024 + tid + i * 256;
            int k = idx >> 8, n = idx & 255;
            float v = Ws[(size_t)k * 256 + n];
            __nv_bfloat16 hi = __float2bfloat16(v);
            g_Wsh[n * 256 + k] = hi;
            g_Wsl[n * 256 + k] = __float2bfloat16(v - __bfloat162float(hi));
        }
    } else {                     // Wm: 32768 elems (256k x 128n), blocks 96..127
        #pragma unroll
        for (int i = 0; i < 4; i++) {
            int idx = (b - 96) * 1024 + tid + i * 256;
            int k = idx >> 7, n = idx & 127;
            float v = Wm[(size_t)k * 128 + n];
            __nv_bfloat16 hi = __float2bfloat16(v);
            g_Wmh[n * 256 + k] = hi;
            g_Wml[n * 256 + k] = __float2bfloat16(v - __bfloat162float(hi));
        }
    }
}

// ---------------------------------------------------------------------------
// kernelA_mma (unchanged, best known): block = 64 rows x 256 cols, 8 warps.
// ---------------------------------------------------------------------------
__global__ __launch_bounds__(256, 1) void kernelA_mma(
    const float* __restrict__ f,
    const float* __restrict__ b1, const float* __restrict__ gamma,
    const float* __restrict__ beta, const float* __restrict__ rmean,
    const float* __restrict__ rvar, int N)
{
    extern __shared__ unsigned char smem[];
    const int tid = threadIdx.x, wid = tid >> 5, lane = tid & 31;
    const int ms = wid & 3, nh = wid >> 2;
    const int g = lane >> 2, kt = lane & 3;
    const int row0 = blockIdx.x * 64;

    float* Pb  = (float*)(smem + PAR_OFF);
    float* Pinv = Pb + 256; float* Pmu = Pinv + 256; float* Pbt = Pmu + 256;
    {
        int c = tid;
        Pb[c]   = b1[c];
        Pinv[c] = gamma[c] * rsqrtf(rvar[c] + 1e-5f);
        Pmu[c]  = rmean[c];
        Pbt[c]  = beta[c];
    }

    // Stage X (64x128 f32 -> bf16 hi/lo)
    #pragma unroll
    for (int i = 0; i < 8; i++) {
        int fi = tid + i * 256;
        int r = fi >> 5, c4 = fi & 31;
        float4 v = make_float4(0.f, 0.f, 0.f, 0.f);
        if (row0 + r < N) v = ((const float4*)(f + (size_t)(row0 + r) * CIN))[c4];
        __nv_bfloat162 h0 = __floats2bfloat162_rn(v.x, v.y);
        __nv_bfloat162 h1 = __floats2bfloat162_rn(v.z, v.w);
        __nv_bfloat162 l0 = __floats2bfloat162_rn(v.x - __bfloat162float(h0.x),
                                                  v.y - __bfloat162float(h0.y));
        __nv_bfloat162 l1 = __floats2bfloat162_rn(v.z - __bfloat162float(h1.x),
                                                  v.w - __bfloat162float(h1.y));
        uint2 hu, lu;
        hu.x = *(uint32_t*)&h0; hu.y = *(uint32_t*)&h1;
        lu.x = *(uint32_t*)&l0; lu.y = *(uint32_t*)&l1;
        *(uint2*)(smem + XH_OFF + r * XS + c4 * 8) = hu;
        *(uint2*)(smem + XL_OFF + r * XS + c4 * 8) = lu;
    }
    // Stage W1
    #pragma unroll
    for (int i = 0; i < 32; i++) {
        int u = tid + i * 256;
        int half_ = u >> 12, r = (u >> 4) & 255, c = u & 15;
        const uint4* src = (const uint4*)(half_ ? (const void*)g_W1l : (const void*)g_W1h);
        *(uint4*)(smem + W_OFF + half_ * WHL + r * WS + c * 16) = src[r * 16 + c];
    }
    __syncthreads();

    float acc[16][4];
    #pragma unroll
    for (int t = 0; t < 16; t++)
        #pragma unroll
        for (int j = 0; j < 4; j++) acc[t][j] = 0.f;

    // GEMM 1: K = 128
    {
        const unsigned char* Ah = smem + XH_OFF + (16 * ms + g) * XS + kt * 4;
        const unsigned char* Al = smem + XL_OFF + (16 * ms + g) * XS + kt * 4;
        const unsigned char* Bb = smem + W_OFF + (nh * 128 + g) * WS + kt * 4;
        #pragma unroll 1
        for (int ks = 0; ks < 8; ks++) {
            const int kb = ks * 32;
            uint32_t ah0 = *(const uint32_t*)(Ah + kb);
            uint32_t ah1 = *(const uint32_t*)(Ah + kb + 8 * XS);
            uint32_t ah2 = *(const uint32_t*)(Ah + kb + 16);
            uint32_t ah3 = *(const uint32_t*)(Ah + kb + 8 * XS + 16);
            uint32_t al0 = *(const uint32_t*)(Al + kb);
            uint32_t al1 = *(const uint32_t*)(Al + kb + 8 * XS);
            uint32_t al2 = *(const uint32_t*)(Al + kb + 16);
            uint32_t al3 = *(const uint32_t*)(Al + kb + 8 * XS + 16);
            #pragma unroll
            for (int t = 0; t < 16; t++) {
                const unsigned char* Bp = Bb + t * 8 * WS + kb;
                uint32_t bh0 = *(const uint32_t*)(Bp);
                uint32_t bh1 = *(const uint32_t*)(Bp + 16);
                uint32_t bl0 = *(const uint32_t*)(Bp + WHL);
                uint32_t bl1 = *(const uint32_t*)(Bp + WHL + 16);
                mma16816(acc[t], ah0, ah1, ah2, ah3, bh0, bh1);
                mma16816(acc[t], ah0, ah1, ah2, ah3, bl0, bl1);
                mma16816(acc[t], al0, al1, al2, al3, bh0, bh1);
            }
        }
    }
    __syncthreads();

    // BN epilogue -> ys hi/lo (smem)
    #pragma unroll
    for (int t = 0; t < 16; t++) {
        const int nc0 = nh * 128 + t * 8 + 2 * kt;
        float2 pb  = *(const float2*)&Pb[nc0];
        float2 pin = *(const float2*)&Pinv[nc0];
        float2 pmu = *(const float2*)&Pmu[nc0];
        float2 pbt = *(const float2*)&Pbt[nc0];
        float y00 = (fmaxf(acc[t][0] + pb.x, 0.f) - pmu.x) * pin.x + pbt.x;
        float y01 = (fmaxf(acc[t][1] + pb.y, 0.f) - pmu.y) * pin.y + pbt.y;
        float y10 = (fmaxf(acc[t][2] + pb.x, 0.f) - pmu.x) * pin.x + pbt.x;
        float y11 = (fmaxf(acc[t][3] + pb.y, 0.f) - pmu.y) * pin.y + pbt.y;
        __nv_bfloat162 h0 = __floats2bfloat162_rn(y00, y01);
        __nv_bfloat162 h1 = __floats2bfloat162_rn(y10, y11);
        __nv_bfloat162 l0 = __floats2bfloat162_rn(y00 - __bfloat162float(h0.x),
                                                  y01 - __bfloat162float(h0.y));
        __nv_bfloat162 l1 = __floats2bfloat162_rn(y10 - __bfloat162float(h1.x),
                                                  y11 - __bfloat162float(h1.y));
        const int r0 = 16 * ms + g;
        *(uint32_t*)(smem + YSH_OFF + r0 * YS + nc0 * 2)       = *(uint32_t*)&h0;
        *(uint32_t*)(smem + YSH_OFF + (r0 + 8) * YS + nc0 * 2) = *(uint32_t*)&h1;
        *(uint32_t*)(smem + YSL_OFF + r0 * YS + nc0 * 2)       = *(uint32_t*)&l0;
        *(uint32_t*)(smem + YSL_OFF + (r0 + 8) * YS + nc0 * 2) = *(uint32_t*)&l1;
    }

    // GEMM 2: K = 256 in 2 staged chunks
    #pragma unroll
    for (int t = 0; t < 16; t++)
        #pragma unroll
        for (int j = 0; j < 4; j++) acc[t][j] = 0.f;

    #pragma unroll 1
    for (int chunk = 0; chunk < 2; chunk++) {
        __syncthreads();
        #pragma unroll
        for (int i = 0; i < 32; i++) {
            int u = tid + i * 256;
            int half_ = u >> 12, r = (u >> 4) & 255, c = u & 15;
            const unsigned char* src =
                (const unsigned char*)(half_ ? (const void*)g_Wsl : (const void*)g_Wsh)
                + (size_t)r * 512 + chunk * 256 + c * 16;
            *(uint4*)(smem + W_OFF + half_ * WHL + r * WS + c * 16) = *(const uint4*)src;
        }
        __syncthreads();

        const unsigned char* Ah = smem + YSH_OFF + (16 * ms + g) * YS + chunk * 256 + kt * 4;
        const unsigned char* Al = smem + YSL_OFF + (16 * ms + g) * YS + chunk * 256 + kt * 4;
        const unsigned char* Bb = smem + W_OFF + (nh * 128 + g) * WS + kt * 4;
        #pragma unroll 1
        for (int ks = 0; ks < 8; ks++) {
            const int kb = ks * 32;
            uint32_t ah0 = *(const uint32_t*)(Ah + kb);
            uint32_t ah1 = *(const uint32_t*)(Ah + kb + 8 * YS);
            uint32_t ah2 = *(const uint32_t*)(Ah + kb + 16);
            uint32_t ah3 = *(const uint32_t*)(Ah + kb + 8 * YS + 16);
            uint32_t al0 = *(const uint32_t*)(Al + kb);
            uint32_t al1 = *(const uint32_t*)(Al + kb + 8 * YS);
            uint32_t al2 = *(const uint32_t*)(Al + kb + 16);
            uint32_t al3 = *(const uint32_t*)(Al + kb + 8 * YS + 16);
            #pragma unroll
            for (int t = 0; t < 16; t++) {
                const unsigned char* Bp = Bb + t * 8 * WS + kb;
                uint32_t bh0 = *(const uint32_t*)(Bp);
                uint32_t bh1 = *(const uint32_t*)(Bp + 16);
                uint32_t bl0 = *(const uint32_t*)(Bp + WHL);
                uint32_t bl1 = *(const uint32_t*)(Bp + WHL + 16);
                mma16816(acc[t], ah0, ah1, ah2, ah3, bh0, bh1);
                mma16816(acc[t], ah0, ah1, ah2, ah3, bl0, bl1);
                mma16816(acc[t], al0, al1, al2, al3, bh0, bh1);
            }
        }
    }

    // Final epilogue: e = exp(z), q = e*y; fp16 interleaved stores
    #pragma unroll
    for (int t = 0; t < 16; t++) {
        const int nc0 = nh * 128 + t * 8 + 2 * kt;
        const int r0 = 16 * ms + g;
        uint32_t yh0 = *(const uint32_t*)(smem + YSH_OFF + r0 * YS + nc0 * 2);
        uint32_t yl0 = *(const uint32_t*)(smem + YSL_OFF + r0 * YS + nc0 * 2);
        uint32_t yh1 = *(const uint32_t*)(smem + YSH_OFF + (r0 + 8) * YS + nc0 * 2);
        uint32_t yl1 = *(const uint32_t*)(smem + YSL_OFF + (r0 + 8) * YS + nc0 * 2);
        __nv_bfloat162 h0 = *(__nv_bfloat162*)&yh0, l0 = *(__nv_bfloat162*)&yl0;
        __nv_bfloat162 h1 = *(__nv_bfloat162*)&yh1, l1 = *(__nv_bfloat162*)&yl1;
        float y00 = __bfloat162float(h0.x) + __bfloat162float(l0.x);
        float y01 = __bfloat162float(h0.y) + __bfloat162float(l0.y);
        float y10 = __bfloat162float(h1.x) + __bfloat162float(l1.x);
        float y11 = __bfloat162float(h1.y) + __bfloat162float(l1.y);
        float e00 = __expf(acc[t][0]), e01 = __expf(acc[t][1]);
        float e10 = __expf(acc[t][2]), e11 = __expf(acc[t][3]);
        int gr0 = row0 + r0, gr1 = gr0 + 8;
        if (gr0 < N) {
            *(__half2*)(g_eq + (size_t)gr0 * 512 + nc0)       = __floats2half2_rn(e00, e01);
            *(__half2*)(g_eq + (size_t)gr0 * 512 + 256 + nc0) = __floats2half2_rn(e00 * y00, e01 * y01);
        }
        if (gr1 < N) {
            *(__half2*)(g_eq + (size_t)gr1 * 512 + nc0)       = __floats2half2_rn(e10, e11);
            *(__half2*)(g_eq + (size_t)gr1 * 512 + 256 + nc0) = __floats2half2_rn(e10 * y10, e11 * y11);
        }
    }
}

// ---------------------------------------------------------------------------
// kernelB1 (unchanged): gather only; warp per node; feat -> bf16 hi/lo global.
// ---------------------------------------------------------------------------
__global__ __launch_bounds__(256) void kernelB1(
    const void* __restrict__ idxp, int N)
{
    const int wl   = threadIdx.x >> 5;
    const int lane = threadIdx.x & 31;
    const int n    = blockIdx.x * 8 + wl;
    if (n >= N) return;

    const int is64 = g_idx64;

    int my = 0;
    if (lane < KNB) {
        if (is64) my = (int)((const long long*)idxp)[(size_t)n * KNB + lane];
        else      my = ((const int*)idxp)[(size_t)n * KNB + lane];
    }
    int nb[KNB];
    #pragma unroll
    for (int k = 0; k < KNB; k++)
        nb[k] = __shfl_sync(0xffffffffu, my, k);

    float den[8], num[8];
    #pragma unroll
    for (int q = 0; q < 8; q++) { den[q] = 0.f; num[q] = 0.f; }

    #pragma unroll 4
    for (int k = 0; k < KNB; k++) {
        const uint4* row = (const uint4*)(g_eq + (size_t)nb[k] * 512);
        uint4 ev = row[lane];
        uint4 qv = row[32 + lane];
        const __half2* eh = (const __half2*)&ev;
        const __half2* qh = (const __half2*)&qv;
        #pragma unroll
        for (int j = 0; j < 4; j++) {
            float2 fe = __half22float2(eh[j]);
            float2 fq = __half22float2(qh[j]);
            den[2*j]   += fe.x;  den[2*j+1] += fe.y;
            num[2*j]   += fq.x;  num[2*j+1] += fq.y;
        }
    }

    uint32_t hw[4], lw[4];
    #pragma unroll
    for (int j = 0; j < 4; j++) {
        float f0 = num[2*j]   / den[2*j];
        float f1 = num[2*j+1] / den[2*j+1];
        __nv_bfloat162 hh = __floats2bfloat162_rn(f0, f1);
        __nv_bfloat162 ll = __floats2bfloat162_rn(f0 - __bfloat162float(hh.x),
                                                  f1 - __bfloat162float(hh.y));
        hw[j] = *(uint32_t*)&hh;
        lw[j] = *(uint32_t*)&ll;
    }
    *(uint4*)(g_fh + (size_t)n * 256 + 8 * lane) = make_uint4(hw[0], hw[1], hw[2], hw[3]);
    *(uint4*)(g_fl + (size_t)n * 256 + 8 * lane) = make_uint4(lw[0], lw[1], lw[2], lw[3]);
}

// ---------------------------------------------------------------------------
// kernelC v2: out(64x128) = feat(64x256) @ Wm + bm.
// smem = feat only (67.6 KB) -> 2 blocks/SM (16 warps). B-frags read directly
// from g_Wmh/g_Wml (128 KB, shared by all blocks -> L1/L2-hot). Single flat
// 16-step K loop, no Wm staging, no extra syncs.
// ---------------------------------------------------------------------------
__global__ __launch_bounds__(256, 2) void kernelC(
    const float* __restrict__ bm,
    float* __restrict__ out,
    int N)
{
    extern __shared__ unsigned char smem[];
    const int tid = threadIdx.x, wid = tid >> 5, lane = tid & 31;
    const int ms = wid & 3, nh = wid >> 2;
    const int g = lane >> 2, kt = lane & 3;
    const int row0 = blockIdx.x * 64;

    // Stage feat hi/lo: 64 rows x 512B each half, stride 528
    #pragma unroll
    for (int i = 0; i < 8; i++) {
        int t = tid + i * 256;            // 2048 uint4 per half
        int r = t >> 5, c = t & 31;
        int gr = row0 + r;
        uint4 vh = make_uint4(0, 0, 0, 0), vl = make_uint4(0, 0, 0, 0);
        if (gr < N) {
            vh = *(const uint4*)(g_fh + (size_t)gr * 256 + c * 8);
            vl = *(const uint4*)(g_fl + (size_t)gr * 256 + c * 8);
        }
        *(uint4*)(smem + C_FH + r * 528 + c * 16) = vh;
        *(uint4*)(smem + C_FL + r * 528 + c * 16) = vl;
    }
    __syncthreads();

    float acc[8][4];
    #pragma unroll
    for (int t = 0; t < 8; t++)
        #pragma unroll
        for (int j = 0; j < 4; j++) acc[t][j] = 0.f;

    const unsigned char* Ah = smem + C_FH + (16 * ms + g) * 528 + kt * 4;
    const unsigned char* Al = smem + C_FL + (16 * ms + g) * 528 + kt * 4;
    // B base: row (nh*64 + g), element offset 2*kt within k
    const __nv_bfloat16* Bh0 = g_Wmh + (size_t)(nh * 64 + g) * 256 + 2 * kt;
    const __nv_bfloat16* Bl0 = g_Wml + (size_t)(nh * 64 + g) * 256 + 2 * kt;

    #pragma unroll 2
    for (int ks = 0; ks < 16; ks++) {
        const int kb = ks * 32;
        uint32_t ah0 = *(const uint32_t*)(Ah + kb);
        uint32_t ah1 = *(const uint32_t*)(Ah + kb + 8 * 528);
        uint32_t ah2 = *(const uint32_t*)(Ah + kb + 16);
        uint32_t ah3 = *(const uint32_t*)(Ah + kb + 8 * 528 + 16);
        uint32_t al0 = *(const uint32_t*)(Al + kb);
        uint32_t al1 = *(const uint32_t*)(Al + kb + 8 * 528);
        uint32_t al2 = *(const uint32_t*)(Al + kb + 16);
        uint32_t al3 = *(const uint32_t*)(Al + kb + 8 * 528 + 16);
        #pragma unroll
        for (int t = 0; t < 8; t++) {
            const __nv_bfloat16* Bh = Bh0 + t * 8 * 256 + ks * 16;
            const __nv_bfloat16* Bl = Bl0 + t * 8 * 256 + ks * 16;
            uint32_t bh0 = *(const uint32_t*)(Bh);
            uint32_t bh1 = *(const uint32_t*)(Bh + 8);
            uint32_t bl0 = *(const uint32_t*)(Bl);
            uint32_t bl1 = *(const uint32_t*)(Bl + 8);
            mma16816(acc[t], ah0, ah1, ah2, ah3, bh0, bh1);
            mma16816(acc[t], ah0, ah1, ah2, ah3, bl0, bl1);
            mma16816(acc[t], al0, al1, al2, al3, bh0, bh1);
        }
    }

    // Epilogue: D rows = row0 + 16ms + g (+8); cols = nh*64 + t*8 + 2kt
    #pragma unroll
    for (int t = 0; t < 8; t++) {
        const int c0 = nh * 64 + t * 8 + 2 * kt;
        float2 bb = *(const float2*)(bm + c0);
        int n0 = row0 + 16 * ms + g;
        int n1 = n0 + 8;
        if (n0 < N)
            *(float2*)(out + (size_t)n0 * COUT + c0) =
                make_float2(acc[t][0] + bb.x, acc[t][1] + bb.y);
        if (n1 < N)
            *(float2*)(out + (size_t)n1 * COUT + c0) =
                make_float2(acc[t][2] + bb.x, acc[t][3] + bb.y);
    }
}

// ---------------------------------------------------------------------------
// Launch: memset(harness), prep, A, B1, C  -> ncu slot #5 = kernelC
// ---------------------------------------------------------------------------
extern "C" void kernel_launch(void* const* d_in, const int* in_sizes, int n_in,
                              void* d_out, int out_size)
{
    const float* f     = (const float*)d_in[0];
    const void*  idxp  = (const void*) d_in[1];
    const float* W1    = (const float*)d_in[2];
    const float* b1    = (const float*)d_in[3];
    const float* gamma = (const float*)d_in[4];
    const float* beta  = (const float*)d_in[5];
    const float* rmean = (const float*)d_in[6];
    const float* rvar  = (const float*)d_in[7];
    const float* Ws    = (const float*)d_in[8];
    const float* Wm    = (const float*)d_in[9];
    const float* bm    = (const float*)d_in[10];
    float* out = (float*)d_out;

    const int N = in_sizes[0] / CIN;

    static int attr_set = 0;
    if (!attr_set) {
        cudaFuncSetAttribute(kernelA_mma,
                             cudaFuncAttributeMaxDynamicSharedMemorySize, SMEM_TOTAL);
        cudaFuncSetAttribute(kernelC,
                             cudaFuncAttributeMaxDynamicSharedMemorySize, C_SMEM);
        attr_set = 1;
    }

    prep_kernel<<<128, 256>>>(W1, Ws, Wm, (const unsigned int*)idxp);
    kernelA_mma<<<(N + 63) / 64, 256, SMEM_TOTAL>>>(f, b1, gamma, beta, rmean, rvar, N);
    kernelB1<<<(N + 7) / 8, 256>>>(idxp, N);
    kernelC<<<(N + 63) / 64, 256, C_SMEM>>>(bm, out, N);
}

// round 15
// speedup vs baseline: 1.2963x; 1.2963x over previous
#include <cuda_runtime.h>
#include <cuda_bf16.h>
#include <cuda_fp16.h>
#include <cstdint>

// Problem constants (fixed by the dataset)
#define NMAX 50000
#define CIN  128
#define C2   256
#define COUT 128
#define KNB  16

// Scratch (static device arrays; no allocation):
__device__ __half g_eq[(size_t)NMAX * 512];       // [node]: 256 e | 256 q (fp16)
__device__ __nv_bfloat16 g_fh[(size_t)NMAX * 256]; // feat hi (bf16)
__device__ __nv_bfloat16 g_fl[(size_t)NMAX * 256]; // feat lo
__device__ __nv_bfloat16 g_W1h[256 * 128];        // W1^T hi  [n][k]
__device__ __nv_bfloat16 g_W1l[256 * 128];
__device__ __nv_bfloat16 g_Wsh[256 * 256];        // Ws^T hi  [n][k]
__device__ __nv_bfloat16 g_Wsl[256 * 256];
__device__ __nv_bfloat16 g_Wmh[128 * 256];        // Wm^T hi  [n][k]
__device__ __nv_bfloat16 g_Wml[128 * 256];
__device__ int g_idx64;

// ---------------------------------------------------------------------------
// mma.sync m16n8k16 bf16 (baseline PTX, valid on compute_103 virtual arch)
// ---------------------------------------------------------------------------
__device__ __forceinline__ void mma16816(float* d,
    uint32_t a0, uint32_t a1, uint32_t a2, uint32_t a3,
    uint32_t b0, uint32_t b1)
{
    asm volatile(
        "mma.sync.aligned.m16n8k16.row.col.f32.bf16.bf16.f32 "
        "{%0,%1,%2,%3}, {%4,%5,%6,%7}, {%8,%9}, {%0,%1,%2,%3};"
        : "+f"(d[0]), "+f"(d[1]), "+f"(d[2]), "+f"(d[3])
        : "r"(a0), "r"(a1), "r"(a2), "r"(a3), "r"(b0), "r"(b1));
}

// SMEM layout for kernelA (bytes). Strides 272/528 ≡ 4 mod 32 words.
#define XS   272
#define XH_OFF 0
#define XL_OFF 17408              // 64*272
#define YS   528
#define YSH_OFF 0
#define YSL_OFF 33792             // 64*528
#define WS   272
#define W_OFF 69632
#define WHL  69632                // 256*272
#define PAR_OFF 208896
#define SMEM_TOTAL 212992

// SMEM layout for kernelC v4: feat (67584) + Wm 64k-subchunk (2 x 18432)
#define C_FH  0                   // feat hi: 64*528 = 33792
#define C_FL  33792               // feat lo
#define C_W   67584               // Wm sub-chunk: hi 128*144, lo follows
#define C_WHALF 18432             // 128*144
#define C_SMEM 104448             // <= 113.5KB -> 2 blocks/SM

// ---------------------------------------------------------------------------
// Prep: pack W1^T, Ws^T, Wm^T bf16 hi/lo, [n][k]; idx dtype detect. 128 blks.
// ---------------------------------------------------------------------------
__global__ __launch_bounds__(256) void prep_kernel(
    const float* __restrict__ W1,
    const float* __restrict__ Ws,
    const float* __restrict__ Wm,
    const unsigned int* __restrict__ idxraw)
{
    const int b = blockIdx.x, tid = threadIdx.x;
    if (b == 0 && tid == 0) {   // int64 -> every odd 32-bit word zero
        int is64 = 1;
        #pragma unroll 1
        for (int t = 1; t < 256; t += 2)
            if (idxraw[t] != 0u) { is64 = 0; break; }
        g_idx64 = is64;
    }
    if (b < 32) {                // W1: 32768 elems, 1024 per block
        #pragma unroll
        for (int i = 0; i < 4; i++) {
            int idx = b * 1024 + tid + i * 256;
            int k = idx >> 8, n = idx & 255;
            float v = W1[(size_t)k * 256 + n];
            __nv_bfloat16 hi = __float2bfloat16(v);
            g_W1h[n * 128 + k] = hi;
            g_W1l[n * 128 + k] = __float2bfloat16(v - __bfloat162float(hi));
        }
    } else if (b < 96) {         // Ws: 65536 elems, blocks 32..95
        #pragma unroll
        for (int i = 0; i < 4; i++) {
            int idx = (b - 32) * 1024 + tid + i * 256;
            int k = idx >> 8, n = idx & 255;
            float v = Ws[(size_t)k * 256 + n];
            __nv_bfloat16 hi = __float2bfloat16(v);
            g_Wsh[n * 256 + k] = hi;
            g_Wsl[n * 256 + k] = __float2bfloat16(v - __bfloat162float(hi));
        }
    } else {                     // Wm: 32768 elems (256k x 128n), blocks 96..127
        #pragma unroll
        for (int i = 0; i < 4; i++) {
            int idx = (b - 96) * 1024 + tid + i * 256;
            int k = idx >> 7, n = idx & 127;
            float v = Wm[(size_t)k * 128 + n];
            __nv_bfloat16 hi = __float2bfloat16(v);
            g_Wmh[n * 256 + k] = hi;
            g_Wml[n * 256 + k] = __float2bfloat16(v - __bfloat162float(hi));
        }
    }
}

// ---------------------------------------------------------------------------
// kernelA_mma (unchanged, best known): block = 64 rows x 256 cols, 8 warps.
// ---------------------------------------------------------------------------
__global__ __launch_bounds__(256, 1) void kernelA_mma(
    const float* __restrict__ f,
    const float* __restrict__ b1, const float* __restrict__ gamma,
    const float* __restrict__ beta, const float* __restrict__ rmean,
    const float* __restrict__ rvar, int N)
{
    extern __shared__ unsigned char smem[];
    const int tid = threadIdx.x, wid = tid >> 5, lane = tid & 31;
    const int ms = wid & 3, nh = wid >> 2;
    const int g = lane >> 2, kt = lane & 3;
    const int row0 = blockIdx.x * 64;

    float* Pb  = (float*)(smem + PAR_OFF);
    float* Pinv = Pb + 256; float* Pmu = Pinv + 256; float* Pbt = Pmu + 256;
    {
        int c = tid;
        Pb[c]   = b1[c];
        Pinv[c] = gamma[c] * rsqrtf(rvar[c] + 1e-5f);
        Pmu[c]  = rmean[c];
        Pbt[c]  = beta[c];
    }

    // Stage X (64x128 f32 -> bf16 hi/lo)
    #pragma unroll
    for (int i = 0; i < 8; i++) {
        int fi = tid + i * 256;
        int r = fi >> 5, c4 = fi & 31;
        float4 v = make_float4(0.f, 0.f, 0.f, 0.f);
        if (row0 + r < N) v = ((const float4*)(f + (size_t)(row0 + r) * CIN))[c4];
        __nv_bfloat162 h0 = __floats2bfloat162_rn(v.x, v.y);
        __nv_bfloat162 h1 = __floats2bfloat162_rn(v.z, v.w);
        __nv_bfloat162 l0 = __floats2bfloat162_rn(v.x - __bfloat162float(h0.x),
                                                  v.y - __bfloat162float(h0.y));
        __nv_bfloat162 l1 = __floats2bfloat162_rn(v.z - __bfloat162float(h1.x),
                                                  v.w - __bfloat162float(h1.y));
        uint2 hu, lu;
        hu.x = *(uint32_t*)&h0; hu.y = *(uint32_t*)&h1;
        lu.x = *(uint32_t*)&l0; lu.y = *(uint32_t*)&l1;
        *(uint2*)(smem + XH_OFF + r * XS + c4 * 8) = hu;
        *(uint2*)(smem + XL_OFF + r * XS + c4 * 8) = lu;
    }
    // Stage W1
    #pragma unroll
    for (int i = 0; i < 32; i++) {
        int u = tid + i * 256;
        int half_ = u >> 12, r = (u >> 4) & 255, c = u & 15;
        const uint4* src = (const uint4*)(half_ ? (const void*)g_W1l : (const void*)g_W1h);
        *(uint4*)(smem + W_OFF + half_ * WHL + r * WS + c * 16) = src[r * 16 + c];
    }
    __syncthreads();

    float acc[16][4];
    #pragma unroll
    for (int t = 0; t < 16; t++)
        #pragma unroll
        for (int j = 0; j < 4; j++) acc[t][j] = 0.f;

    // GEMM 1: K = 128
    {
        const unsigned char* Ah = smem + XH_OFF + (16 * ms + g) * XS + kt * 4;
        const unsigned char* Al = smem + XL_OFF + (16 * ms + g) * XS + kt * 4;
        const unsigned char* Bb = smem + W_OFF + (nh * 128 + g) * WS + kt * 4;
        #pragma unroll 1
        for (int ks = 0; ks < 8; ks++) {
            const int kb = ks * 32;
            uint32_t ah0 = *(const uint32_t*)(Ah + kb);
            uint32_t ah1 = *(const uint32_t*)(Ah + kb + 8 * XS);
            uint32_t ah2 = *(const uint32_t*)(Ah + kb + 16);
            uint32_t ah3 = *(const uint32_t*)(Ah + kb + 8 * XS + 16);
            uint32_t al0 = *(const uint32_t*)(Al + kb);
            uint32_t al1 = *(const uint32_t*)(Al + kb + 8 * XS);
            uint32_t al2 = *(const uint32_t*)(Al + kb + 16);
            uint32_t al3 = *(const uint32_t*)(Al + kb + 8 * XS + 16);
            #pragma unroll
            for (int t = 0; t < 16; t++) {
                const unsigned char* Bp = Bb + t * 8 * WS + kb;
                uint32_t bh0 = *(const uint32_t*)(Bp);
                uint32_t bh1 = *(const uint32_t*)(Bp + 16);
                uint32_t bl0 = *(const uint32_t*)(Bp + WHL);
                uint32_t bl1 = *(const uint32_t*)(Bp + WHL + 16);
                mma16816(acc[t], ah0, ah1, ah2, ah3, bh0, bh1);
                mma16816(acc[t], ah0, ah1, ah2, ah3, bl0, bl1);
                mma16816(acc[t], al0, al1, al2, al3, bh0, bh1);
            }
        }
    }
    __syncthreads();

    // BN epilogue -> ys hi/lo (smem)
    #pragma unroll
    for (int t = 0; t < 16; t++) {
        const int nc0 = nh * 128 + t * 8 + 2 * kt;
        float2 pb  = *(const float2*)&Pb[nc0];
        float2 pin = *(const float2*)&Pinv[nc0];
        float2 pmu = *(const float2*)&Pmu[nc0];
        float2 pbt = *(const float2*)&Pbt[nc0];
        float y00 = (fmaxf(acc[t][0] + pb.x, 0.f) - pmu.x) * pin.x + pbt.x;
        float y01 = (fmaxf(acc[t][1] + pb.y, 0.f) - pmu.y) * pin.y + pbt.y;
        float y10 = (fmaxf(acc[t][2] + pb.x, 0.f) - pmu.x) * pin.x + pbt.x;
        float y11 = (fmaxf(acc[t][3] + pb.y, 0.f) - pmu.y) * pin.y + pbt.y;
        __nv_bfloat162 h0 = __floats2bfloat162_rn(y00, y01);
        __nv_bfloat162 h1 = __floats2bfloat162_rn(y10, y11);
        __nv_bfloat162 l0 = __floats2bfloat162_rn(y00 - __bfloat162float(h0.x),
                                                  y01 - __bfloat162float(h0.y));
        __nv_bfloat162 l1 = __floats2bfloat162_rn(y10 - __bfloat162float(h1.x),
                                                  y11 - __bfloat162float(h1.y));
        const int r0 = 16 * ms + g;
        *(uint32_t*)(smem + YSH_OFF + r0 * YS + nc0 * 2)       = *(uint32_t*)&h0;
        *(uint32_t*)(smem + YSH_OFF + (r0 + 8) * YS + nc0 * 2) = *(uint32_t*)&h1;
        *(uint32_t*)(smem + YSL_OFF + r0 * YS + nc0 * 2)       = *(uint32_t*)&l0;
        *(uint32_t*)(smem + YSL_OFF + (r0 + 8) * YS + nc0 * 2) = *(uint32_t*)&l1;
    }

    // GEMM 2: K = 256 in 2 staged chunks
    #pragma unroll
    for (int t = 0; t < 16; t++)
        #pragma unroll
        for (int j = 0; j < 4; j++) acc[t][j] = 0.f;

    #pragma unroll 1
    for (int chunk = 0; chunk < 2; chunk++) {
        __syncthreads();
        #pragma unroll
        for (int i = 0; i < 32; i++) {
            int u = tid + i * 256;
            int half_ = u >> 12, r = (u >> 4) & 255, c = u & 15;
            const unsigned char* src =
                (const unsigned char*)(half_ ? (const void*)g_Wsl : (const void*)g_Wsh)
                + (size_t)r * 512 + chunk * 256 + c * 16;
            *(uint4*)(smem + W_OFF + half_ * WHL + r * WS + c * 16) = *(const uint4*)src;
        }
        __syncthreads();

        const unsigned char* Ah = smem + YSH_OFF + (16 * ms + g) * YS + chunk * 256 + kt * 4;
        const unsigned char* Al = smem + YSL_OFF + (16 * ms + g) * YS + chunk * 256 + kt * 4;
        const unsigned char* Bb = smem + W_OFF + (nh * 128 + g) * WS + kt * 4;
        #pragma unroll 1
        for (int ks = 0; ks < 8; ks++) {
            const int kb = ks * 32;
            uint32_t ah0 = *(const uint32_t*)(Ah + kb);
            uint32_t ah1 = *(const uint32_t*)(Ah + kb + 8 * YS);
            uint32_t ah2 = *(const uint32_t*)(Ah + kb + 16);
            uint32_t ah3 = *(const uint32_t*)(Ah + kb + 8 * YS + 16);
            uint32_t al0 = *(const uint32_t*)(Al + kb);
            uint32_t al1 = *(const uint32_t*)(Al + kb + 8 * YS);
            uint32_t al2 = *(const uint32_t*)(Al + kb + 16);
            uint32_t al3 = *(const uint32_t*)(Al + kb + 8 * YS + 16);
            #pragma unroll
            for (int t = 0; t < 16; t++) {
                const unsigned char* Bp = Bb + t * 8 * WS + kb;
                uint32_t bh0 = *(const uint32_t*)(Bp);
                uint32_t bh1 = *(const uint32_t*)(Bp + 16);
                uint32_t bl0 = *(const uint32_t*)(Bp + WHL);
                uint32_t bl1 = *(const uint32_t*)(Bp + WHL + 16);
                mma16816(acc[t], ah0, ah1, ah2, ah3, bh0, bh1);
                mma16816(acc[t], ah0, ah1, ah2, ah3, bl0, bl1);
                mma16816(acc[t], al0, al1, al2, al3, bh0, bh1);
            }
        }
    }

    // Final epilogue: e = exp(z), q = e*y; fp16 interleaved stores
    #pragma unroll
    for (int t = 0; t < 16; t++) {
        const int nc0 = nh * 128 + t * 8 + 2 * kt;
        const int r0 = 16 * ms + g;
        uint32_t yh0 = *(const uint32_t*)(smem + YSH_OFF + r0 * YS + nc0 * 2);
        uint32_t yl0 = *(const uint32_t*)(smem + YSL_OFF + r0 * YS + nc0 * 2);
        uint32_t yh1 = *(const uint32_t*)(smem + YSH_OFF + (r0 + 8) * YS + nc0 * 2);
        uint32_t yl1 = *(const uint32_t*)(smem + YSL_OFF + (r0 + 8) * YS + nc0 * 2);
        __nv_bfloat162 h0 = *(__nv_bfloat162*)&yh0, l0 = *(__nv_bfloat162*)&yl0;
        __nv_bfloat162 h1 = *(__nv_bfloat162*)&yh1, l1 = *(__nv_bfloat162*)&yl1;
        float y00 = __bfloat162float(h0.x) + __bfloat162float(l0.x);
        float y01 = __bfloat162float(h0.y) + __bfloat162float(l0.y);
        float y10 = __bfloat162float(h1.x) + __bfloat162float(l1.x);
        float y11 = __bfloat162float(h1.y) + __bfloat162float(l1.y);
        float e00 = __expf(acc[t][0]), e01 = __expf(acc[t][1]);
        float e10 = __expf(acc[t][2]), e11 = __expf(acc[t][3]);
        int gr0 = row0 + r0, gr1 = gr0 + 8;
        if (gr0 < N) {
            *(__half2*)(g_eq + (size_t)gr0 * 512 + nc0)       = __floats2half2_rn(e00, e01);
            *(__half2*)(g_eq + (size_t)gr0 * 512 + 256 + nc0) = __floats2half2_rn(e00 * y00, e01 * y01);
        }
        if (gr1 < N) {
            *(__half2*)(g_eq + (size_t)gr1 * 512 + nc0)       = __floats2half2_rn(e10, e11);
            *(__half2*)(g_eq + (size_t)gr1 * 512 + 256 + nc0) = __floats2half2_rn(e10 * y10, e11 * y11);
        }
    }
}

// ---------------------------------------------------------------------------
// kernelB1 (unchanged): gather only; warp per node; feat -> bf16 hi/lo global.
// ---------------------------------------------------------------------------
__global__ __launch_bounds__(256) void kernelB1(
    const void* __restrict__ idxp, int N)
{
    const int wl   = threadIdx.x >> 5;
    const int lane = threadIdx.x & 31;
    const int n    = blockIdx.x * 8 + wl;
    if (n >= N) return;

    const int is64 = g_idx64;

    int my = 0;
    if (lane < KNB) {
        if (is64) my = (int)((const long long*)idxp)[(size_t)n * KNB + lane];
        else      my = ((const int*)idxp)[(size_t)n * KNB + lane];
    }
    int nb[KNB];
    #pragma unroll
    for (int k = 0; k < KNB; k++)
        nb[k] = __shfl_sync(0xffffffffu, my, k);

    float den[8], num[8];
    #pragma unroll
    for (int q = 0; q < 8; q++) { den[q] = 0.f; num[q] = 0.f; }

    #pragma unroll 4
    for (int k = 0; k < KNB; k++) {
        const uint4* row = (const uint4*)(g_eq + (size_t)nb[k] * 512);
        uint4 ev = row[lane];
        uint4 qv = row[32 + lane];
        const __half2* eh = (const __half2*)&ev;
        const __half2* qh = (const __half2*)&qv;
        #pragma unroll
        for (int j = 0; j < 4; j++) {
            float2 fe = __half22float2(eh[j]);
            float2 fq = __half22float2(qh[j]);
            den[2*j]   += fe.x;  den[2*j+1] += fe.y;
            num[2*j]   += fq.x;  num[2*j+1] += fq.y;
        }
    }

    uint32_t hw[4], lw[4];
    #pragma unroll
    for (int j = 0; j < 4; j++) {
        float f0 = num[2*j]   / den[2*j];
        float f1 = num[2*j+1] / den[2*j+1];
        __nv_bfloat162 hh = __floats2bfloat162_rn(f0, f1);
        __nv_bfloat162 ll = __floats2bfloat162_rn(f0 - __bfloat162float(hh.x),
                                                  f1 - __bfloat162float(hh.y));
        hw[j] = *(uint32_t*)&hh;
        lw[j] = *(uint32_t*)&ll;
    }
    *(uint4*)(g_fh + (size_t)n * 256 + 8 * lane) = make_uint4(hw[0], hw[1], hw[2], hw[3]);
    *(uint4*)(g_fl + (size_t)n * 256 + 8 * lane) = make_uint4(lw[0], lw[1], lw[2], lw[3]);
}

// ---------------------------------------------------------------------------
// kernelC v4: out(64x128) = feat(64x256) @ Wm + bm.
// Same staged structure as the proven R13 version, but Wm staged in FOUR
// 64-k sub-chunks (36.9 KB region, stride 144 ≡ 4 mod 32 words) so total
// smem = 104.4 KB -> 2 blocks/SM (16 warps). Syncs overlap across blocks.
// ---------------------------------------------------------------------------
__global__ __launch_bounds__(256, 2) void kernelC(
    const float* __restrict__ bm,
    float* __restrict__ out,
    int N)
{
    extern __shared__ unsigned char smem[];
    const int tid = threadIdx.x, wid = tid >> 5, lane = tid & 31;
    const int ms = wid & 3, nh = wid >> 2;
    const int g = lane >> 2, kt = lane & 3;
    const int row0 = blockIdx.x * 64;

    // Stage feat hi/lo: 64 rows x 512B each half, stride 528
    #pragma unroll
    for (int i = 0; i < 8; i++) {
        int t = tid + i * 256;            // 2048 uint4 per half
        int r = t >> 5, c = t & 31;
        int gr = row0 + r;
        uint4 vh = make_uint4(0, 0, 0, 0), vl = make_uint4(0, 0, 0, 0);
        if (gr < N) {
            vh = *(const uint4*)(g_fh + (size_t)gr * 256 + c * 8);
            vl = *(const uint4*)(g_fl + (size_t)gr * 256 + c * 8);
        }
        *(uint4*)(smem + C_FH + r * 528 + c * 16) = vh;
        *(uint4*)(smem + C_FL + r * 528 + c * 16) = vl;
    }

    float acc[8][4];
    #pragma unroll
    for (int t = 0; t < 8; t++)
        #pragma unroll
        for (int j = 0; j < 4; j++) acc[t][j] = 0.f;

    #pragma unroll 1
    for (int chunk = 0; chunk < 4; chunk++) {
        __syncthreads();   // feat staged (chunk 0) / prior W reads done (1..3)
        // Stage Wm 64-k sub-chunk: 128 n-rows x 128B per half, stride 144
        #pragma unroll
        for (int i = 0; i < 8; i++) {
            int u = tid + i * 256;        // 2048 uint4 (1024 per half)
            int half_ = u >> 10;
            int uu = u & 1023;
            int r = uu >> 3, c = uu & 7;
            const unsigned char* src =
                (const unsigned char*)(half_ ? (const void*)g_Wml : (const void*)g_Wmh)
                + (size_t)r * 512 + chunk * 128 + c * 16;
            *(uint4*)(smem + C_W + half_ * C_WHALF + r * 144 + c * 16) = *(const uint4*)src;
        }
        __syncthreads();

        const unsigned char* Ah = smem + C_FH + (16 * ms + g) * 528 + chunk * 128 + kt * 4;
        const unsigned char* Al = smem + C_FL + (16 * ms + g) * 528 + chunk * 128 + kt * 4;
        const unsigned char* Bb = smem + C_W + (nh * 64 + g) * 144 + kt * 4;
        #pragma unroll
        for (int ks = 0; ks < 4; ks++) {
            const int kb = ks * 32;
            uint32_t ah0 = *(const uint32_t*)(Ah + kb);
            uint32_t ah1 = *(const uint32_t*)(Ah + kb + 8 * 528);
            uint32_t ah2 = *(const uint32_t*)(Ah + kb + 16);
            uint32_t ah3 = *(const uint32_t*)(Ah + kb + 8 * 528 + 16);
            uint32_t al0 = *(const uint32_t*)(Al + kb);
            uint32_t al1 = *(const uint32_t*)(Al + kb + 8 * 528);
            uint32_t al2 = *(const uint32_t*)(Al + kb + 16);
            uint32_t al3 = *(const uint32_t*)(Al + kb + 8 * 528 + 16);
            #pragma unroll
            for (int t = 0; t < 8; t++) {
                const unsigned char* Bp = Bb + t * 8 * 144 + kb;
                uint32_t bh0 = *(const uint32_t*)(Bp);
                uint32_t bh1 = *(const uint32_t*)(Bp + 16);
                uint32_t bl0 = *(const uint32_t*)(Bp + C_WHALF);
                uint32_t bl1 = *(const uint32_t*)(Bp + C_WHALF + 16);
                mma16816(acc[t], ah0, ah1, ah2, ah3, bh0, bh1);
                mma16816(acc[t], ah0, ah1, ah2, ah3, bl0, bl1);
                mma16816(acc[t], al0, al1, al2, al3, bh0, bh1);
            }
        }
    }

    // Epilogue: D rows = row0 + 16ms + g (+8); cols = nh*64 + t*8 + 2kt
    #pragma unroll
    for (int t = 0; t < 8; t++) {
        const int c0 = nh * 64 + t * 8 + 2 * kt;
        float2 bb = *(const float2*)(bm + c0);
        int n0 = row0 + 16 * ms + g;
        int n1 = n0 + 8;
        if (n0 < N)
            *(float2*)(out + (size_t)n0 * COUT + c0) =
                make_float2(acc[t][0] + bb.x, acc[t][1] + bb.y);
        if (n1 < N)
            *(float2*)(out + (size_t)n1 * COUT + c0) =
                make_float2(acc[t][2] + bb.x, acc[t][3] + bb.y);
    }
}

// ---------------------------------------------------------------------------
// Launch: memset(harness), prep, A, B1, C  -> ncu slot #5 = kernelC
// ---------------------------------------------------------------------------
extern "C" void kernel_launch(void* const* d_in, const int* in_sizes, int n_in,
                              void* d_out, int out_size)
{
    const float* f     = (const float*)d_in[0];
    const void*  idxp  = (const void*) d_in[1];
    const float* W1    = (const float*)d_in[2];
    const float* b1    = (const float*)d_in[3];
    const float* gamma = (const float*)d_in[4];
    const float* beta  = (const float*)d_in[5];
    const float* rmean = (const float*)d_in[6];
    const float* rvar  = (const float*)d_in[7];
    const float* Ws    = (const float*)d_in[8];
    const float* Wm    = (const float*)d_in[9];
    const float* bm    = (const float*)d_in[10];
    float* out = (float*)d_out;

    const int N = in_sizes[0] / CIN;

    static int attr_set = 0;
    if (!attr_set) {
        cudaFuncSetAttribute(kernelA_mma,
                             cudaFuncAttributeMaxDynamicSharedMemorySize, SMEM_TOTAL);
        cudaFuncSetAttribute(kernelC,
                             cudaFuncAttributeMaxDynamicSharedMemorySize, C_SMEM);
        attr_set = 1;
    }

    prep_kernel<<<128, 256>>>(W1, Ws, Wm, (const unsigned int*)idxp);
    kernelA_mma<<<(N + 63) / 64, 256, SMEM_TOTAL>>>(f, b1, gamma, beta, rmean, rvar, N);
    kernelB1<<<(N + 7) / 8, 256>>>(idxp, N);
    kernelC<<<(N + 63) / 64, 256, C_SMEM>>>(bm, out, N);
}